// round 1
// baseline (speedup 1.0000x reference)
#include <cuda_runtime.h>
#include <cstdint>
#include <math.h>

#define SEQQ 2048
#define SEQK 2048
#define NB   4
#define NH   16
#define HD   64
#define DIMQ 1024
#define QK_SCALE 0.125f
#define SST  68   // smem row stride (floats) to avoid bank conflicts

// ---- static device scratch (no allocations allowed in kernel_launch) ----
__device__ float         g_S[(size_t)NB * NH * SEQQ * SEQK];   // [bh][i][j] exp-scores, 1 GiB
__device__ float         g_rowsum[(size_t)SEQQ * NB * NH];     // [i][bh]
__device__ float         g_x[(size_t)SEQQ * NB * DIMQ];        // attention output pre-projection
__device__ unsigned char g_M[NB][(size_t)SEQQ * SEQK];         // mask byte planes [b][i*2048+j]

// ---------------------------------------------------------------------------
// Kernel 0: repack mask (i,j,b) int32 -> per-b byte planes (i*2048+j)
// ---------------------------------------------------------------------------
__global__ __launch_bounds__(256) void k_mask(const int* __restrict__ mask) {
    size_t idx = (size_t)blockIdx.x * 256 + threadIdx.x;   // over 2048*2048 (i,j)
    int4 m = ((const int4*)mask)[idx];
    g_M[0][idx] = (m.x != 0);
    g_M[1][idx] = (m.y != 0);
    g_M[2][idx] = (m.z != 0);
    g_M[3][idx] = (m.w != 0);
}

// ---------------------------------------------------------------------------
// Kernel 1: S[bh][i][j] = mask * exp(scale * q_i . k_j), rowsum[i][bh]
// block = (q-tile of 64) x (full k range) for one (b,h). 256 threads, 4x4 micro.
// ---------------------------------------------------------------------------
__global__ __launch_bounds__(256) void k_scores(const float* __restrict__ q,
                                                const float* __restrict__ k) {
    int qt = blockIdx.x;          // 0..31
    int bh = blockIdx.y;          // 0..63
    int b = bh >> 4, h = bh & 15;

    __shared__ float Qs[64][SST];
    __shared__ float Ks[64][SST];
    __shared__ float red[64][17];
    __shared__ unsigned char Ms[64][64];

    int t = threadIdx.x;
    int ty = t >> 4, tx = t & 15;

    const float* qbase = q + (size_t)b * DIMQ + h * HD;
    const float* kbase = k + (size_t)b * DIMQ + h * HD;
    const unsigned char* mplane = g_M[b];
    float* splane = g_S + (size_t)bh * SEQQ * SEQK;

    // load Q tile (64 rows x 64 d), rows contiguous per 16 float4
    #pragma unroll
    for (int r = 0; r < 4; r++) {
        int idx = t + r * 256;
        int row = idx >> 4, d4 = idx & 15;
        float4 v = *(const float4*)(qbase + (size_t)(qt * 64 + row) * (NB * DIMQ) + d4 * 4);
        *(float4*)&Qs[row][d4 * 4] = v;
    }

    float rsum[4] = {0.f, 0.f, 0.f, 0.f};

    for (int kt = 0; kt < 32; kt++) {
        __syncthreads();
        // load K tile and mask tile
        #pragma unroll
        for (int r = 0; r < 4; r++) {
            int idx = t + r * 256;
            int row = idx >> 4, d4 = idx & 15;
            float4 v = *(const float4*)(kbase + (size_t)(kt * 64 + row) * (NB * DIMQ) + d4 * 4);
            *(float4*)&Ks[row][d4 * 4] = v;
        }
        {
            int row = t >> 2, seg = t & 3;
            uint4 mv = *(const uint4*)(mplane + (size_t)(qt * 64 + row) * SEQK + kt * 64 + seg * 16);
            *(uint4*)&Ms[row][seg * 16] = mv;
        }
        __syncthreads();

        float acc[4][4] = {};
        #pragma unroll
        for (int d4 = 0; d4 < 16; d4++) {
            float4 aa[4], bb[4];
            #pragma unroll
            for (int ii = 0; ii < 4; ii++) aa[ii] = *(const float4*)&Qs[4 * ty + ii][d4 * 4];
            #pragma unroll
            for (int jj = 0; jj < 4; jj++) bb[jj] = *(const float4*)&Ks[4 * tx + jj][d4 * 4];
            #pragma unroll
            for (int ii = 0; ii < 4; ii++)
                #pragma unroll
                for (int jj = 0; jj < 4; jj++)
                    acc[ii][jj] += aa[ii].x * bb[jj].x + aa[ii].y * bb[jj].y +
                                   aa[ii].z * bb[jj].z + aa[ii].w * bb[jj].w;
        }

        int gi0 = qt * 64 + 4 * ty;
        int gj0 = kt * 64 + 4 * tx;
        int li0 = 4 * ty, lj0 = 4 * tx;
        #pragma unroll
        for (int ii = 0; ii < 4; ii++) {
            float4 sv;
            float* svp = (float*)&sv;
            #pragma unroll
            for (int jj = 0; jj < 4; jj++) {
                float e = expf(acc[ii][jj] * QK_SCALE) * (float)Ms[li0 + ii][lj0 + jj];
                svp[jj] = e;
                rsum[ii] += e;
            }
            *(float4*)(splane + (size_t)(gi0 + ii) * SEQK + gj0) = sv;
        }
    }

    // reduce row sums across the 16 tx threads sharing each row
    #pragma unroll
    for (int ii = 0; ii < 4; ii++) red[4 * ty + ii][tx] = rsum[ii];
    __syncthreads();
    if (t < 64) {
        float s = 0.f;
        #pragma unroll
        for (int x = 0; x < 16; x++) s += red[t][x];
        g_rowsum[(size_t)(qt * 64 + t) * (NB * NH) + bh] = s;
    }
}

// ---------------------------------------------------------------------------
// Kernel 2: x[i][b][h*64+d] = (1/rowsum) * sum_j S[bh][i][j] * v[j][b][h*64+d]
// ---------------------------------------------------------------------------
__global__ __launch_bounds__(256) void k_av(const float* __restrict__ v) {
    int it = blockIdx.x;          // 0..31
    int bh = blockIdx.y;          // 0..63
    int b = bh >> 4, h = bh & 15;

    __shared__ float As[64][SST];
    __shared__ float Vs[64][SST];

    int t = threadIdx.x;
    int ty = t >> 4, tx = t & 15;

    const float* splane = g_S + (size_t)bh * SEQQ * SEQK;
    const float* vbase = v + (size_t)b * DIMQ + h * HD;

    float acc[4][4] = {};

    for (int kt = 0; kt < 32; kt++) {
        __syncthreads();
        #pragma unroll
        for (int r = 0; r < 4; r++) {
            int idx = t + r * 256;
            int row = idx >> 4, c4 = idx & 15;
            *(float4*)&As[row][c4 * 4] =
                *(const float4*)(splane + (size_t)(it * 64 + row) * SEQK + kt * 64 + c4 * 4);
            *(float4*)&Vs[row][c4 * 4] =
                *(const float4*)(vbase + (size_t)(kt * 64 + row) * (NB * DIMQ) + c4 * 4);
        }
        __syncthreads();

        #pragma unroll
        for (int j4 = 0; j4 < 16; j4++) {
            float av[4][4], bv[4][4];
            #pragma unroll
            for (int ii = 0; ii < 4; ii++) {
                float4 tmp = *(const float4*)&As[4 * ty + ii][j4 * 4];
                av[ii][0] = tmp.x; av[ii][1] = tmp.y; av[ii][2] = tmp.z; av[ii][3] = tmp.w;
            }
            #pragma unroll
            for (int r = 0; r < 4; r++) {
                float4 tmp = *(const float4*)&Vs[j4 * 4 + r][4 * tx];
                bv[r][0] = tmp.x; bv[r][1] = tmp.y; bv[r][2] = tmp.z; bv[r][3] = tmp.w;
            }
            #pragma unroll
            for (int ii = 0; ii < 4; ii++)
                #pragma unroll
                for (int jj = 0; jj < 4; jj++)
                    acc[ii][jj] += av[ii][0] * bv[0][jj] + av[ii][1] * bv[1][jj] +
                                   av[ii][2] * bv[2][jj] + av[ii][3] * bv[3][jj];
        }
    }

    #pragma unroll
    for (int ii = 0; ii < 4; ii++) {
        int gi = it * 64 + 4 * ty + ii;
        float rinv = 1.0f / g_rowsum[(size_t)gi * (NB * NH) + bh];
        float4 o;
        o.x = acc[ii][0] * rinv; o.y = acc[ii][1] * rinv;
        o.z = acc[ii][2] * rinv; o.w = acc[ii][3] * rinv;
        *(float4*)(g_x + (size_t)(gi * NB + b) * DIMQ + h * HD + 4 * tx) = o;
    }
}

// ---------------------------------------------------------------------------
// Kernel 3: normalized attn write with transpose to [i][j][b][h] layout.
// block = one i, one 64-wide j tile, all 64 (b,h) planes. Coalesced both ways.
// ---------------------------------------------------------------------------
__global__ __launch_bounds__(256) void k_attnT(float* __restrict__ attn) {
    int i = blockIdx.x;           // 0..2047
    int jt = blockIdx.y;          // 0..31

    __shared__ float T[64][SST];  // [j_local][c]  (c = b*16+h)
    __shared__ float rinv_s[64];

    int t = threadIdx.x;
    if (t < 64) rinv_s[t] = 1.0f / g_rowsum[(size_t)i * 64 + t];

    {
        int c = t >> 2, l4 = t & 3;
        const float* src = g_S + ((size_t)c * SEQQ + i) * SEQK + jt * 64 + l4 * 16;
        #pragma unroll
        for (int r = 0; r < 4; r++) {
            float4 vv = *(const float4*)(src + r * 4);
            int j = l4 * 16 + r * 4;
            T[j + 0][c] = vv.x; T[j + 1][c] = vv.y;
            T[j + 2][c] = vv.z; T[j + 3][c] = vv.w;
        }
    }
    __syncthreads();
    {
        int c0 = (t & 15) * 4;
        int jb = t >> 4;
        #pragma unroll
        for (int r = 0; r < 4; r++) {
            int j = jb + r * 16;
            float4 o;
            o.x = T[j][c0 + 0] * rinv_s[c0 + 0];
            o.y = T[j][c0 + 1] * rinv_s[c0 + 1];
            o.z = T[j][c0 + 2] * rinv_s[c0 + 2];
            o.w = T[j][c0 + 3] * rinv_s[c0 + 3];
            *(float4*)(attn + ((size_t)i * SEQK + jt * 64 + j) * 64 + c0) = o;
        }
    }
}

// ---------------------------------------------------------------------------
// Kernel 4: out = x @ W^T + bias.  (8192 x 1024) @ (1024 x 1024)^T
// ---------------------------------------------------------------------------
__global__ __launch_bounds__(256) void k_proj(const float* __restrict__ W,
                                              const float* __restrict__ bias,
                                              float* __restrict__ out) {
    int rt = blockIdx.x;          // 0..127 (64 rows each of 8192)
    int nt = blockIdx.y;          // 0..15

    __shared__ float Xs[64][SST];
    __shared__ float Ws[64][SST];

    int t = threadIdx.x;
    int ty = t >> 4, tx = t & 15;

    float acc[4][4] = {};

    for (int mt = 0; mt < 16; mt++) {
        __syncthreads();
        #pragma unroll
        for (int r = 0; r < 4; r++) {
            int idx = t + r * 256;
            int row = idx >> 4, m4 = idx & 15;
            *(float4*)&Xs[row][m4 * 4] =
                *(const float4*)(g_x + (size_t)(rt * 64 + row) * DIMQ + mt * 64 + m4 * 4);
            *(float4*)&Ws[row][m4 * 4] =
                *(const float4*)(W + (size_t)(nt * 64 + row) * DIMQ + mt * 64 + m4 * 4);
        }
        __syncthreads();

        #pragma unroll
        for (int m4 = 0; m4 < 16; m4++) {
            float4 aa[4], bb[4];
            #pragma unroll
            for (int ii = 0; ii < 4; ii++) aa[ii] = *(const float4*)&Xs[4 * ty + ii][m4 * 4];
            #pragma unroll
            for (int jj = 0; jj < 4; jj++) bb[jj] = *(const float4*)&Ws[4 * tx + jj][m4 * 4];
            #pragma unroll
            for (int ii = 0; ii < 4; ii++)
                #pragma unroll
                for (int jj = 0; jj < 4; jj++)
                    acc[ii][jj] += aa[ii].x * bb[jj].x + aa[ii].y * bb[jj].y +
                                   aa[ii].z * bb[jj].z + aa[ii].w * bb[jj].w;
        }
    }

    float4 bb4 = *(const float4*)(bias + nt * 64 + 4 * tx);
    #pragma unroll
    for (int ii = 0; ii < 4; ii++) {
        int row = rt * 64 + 4 * ty + ii;
        float4 o;
        o.x = acc[ii][0] + bb4.x; o.y = acc[ii][1] + bb4.y;
        o.z = acc[ii][2] + bb4.z; o.w = acc[ii][3] + bb4.w;
        *(float4*)(out + (size_t)row * DIMQ + nt * 64 + 4 * tx) = o;
    }
}

// ---------------------------------------------------------------------------
extern "C" void kernel_launch(void* const* d_in, const int* in_sizes, int n_in,
                              void* d_out, int out_size) {
    const float* q    = (const float*)d_in[0];
    const float* k    = (const float*)d_in[1];
    const float* v    = (const float*)d_in[2];
    const int*   mask = (const int*)d_in[3];   // bool -> int32/f32; !=0 works for both
    const float* W    = (const float*)d_in[4];
    const float* bias = (const float*)d_in[5];
    float* out = (float*)d_out;

    k_mask<<<(SEQQ * SEQK) / 256, 256>>>(mask);
    k_scores<<<dim3(SEQQ / 64, NB * NH), 256>>>(q, k);
    k_av<<<dim3(SEQQ / 64, NB * NH), 256>>>(v);
    k_proj<<<dim3(SEQQ * NB / 64, DIMQ / 64), 256>>>(W, bias, out);

    const long long OUT_ELEMS  = (long long)SEQQ * NB * DIMQ;           // 8,388,608
    const long long ATTN_ELEMS = (long long)SEQQ * SEQK * NB * NH;      // 268,435,456
    if ((long long)out_size >= OUT_ELEMS + ATTN_ELEMS) {
        float* attn = out + OUT_ELEMS;
        k_attnT<<<dim3(SEQQ, SEQK / 64), 256>>>(attn);
    }
}

// round 3
// speedup vs baseline: 2.3092x; 2.3092x over previous
#include <cuda_runtime.h>
#include <cuda_bf16.h>
#include <cstdint>
#include <math.h>

#define SEQQ 2048
#define SEQK 2048
#define NB   4
#define NH   16
#define HD   64
#define DIMQ 1024
#define QK_SCALE 0.125f
#define SST  72   // smem tile row stride in bf16 elems (144B -> ldmatrix conflict-free)

// ---------------- static device scratch ----------------
__device__ uint32_t g_S[(size_t)NB * NH * SEQQ * SEQK];     // packed bf16 hi|lo exp-scores, 1 GiB
__device__ float    g_rowsum[(size_t)SEQQ * NB * NH];       // [i][bh]
__device__ uint32_t g_xp[(size_t)SEQQ * NB * DIMQ];         // packed bf16 hi|lo attention out
__device__ uint32_t g_Vt[(size_t)NB * NH * HD * SEQK];      // packed V transposed [bh][d][j]
__device__ unsigned char g_M[NB][(size_t)SEQQ * SEQK];      // mask byte planes

// ---------------- helpers ----------------
__device__ __forceinline__ uint32_t smem_u32(const void* p) {
    uint32_t a;
    asm("{ .reg .u64 t; cvta.to.shared.u64 t, %1; cvt.u32.u64 %0, t; }" : "=r"(a) : "l"(p));
    return a;
}
__device__ __forceinline__ void ldsm4(uint32_t r[4], uint32_t addr) {
    asm volatile("ldmatrix.sync.aligned.m8n8.x4.shared.b16 {%0,%1,%2,%3}, [%4];"
                 : "=r"(r[0]), "=r"(r[1]), "=r"(r[2]), "=r"(r[3]) : "r"(addr));
}
__device__ __forceinline__ void mma_bf16(float* c, const uint32_t* a, uint32_t b0, uint32_t b1) {
    asm volatile("mma.sync.aligned.m16n8k16.row.col.f32.bf16.bf16.f32 "
                 "{%0,%1,%2,%3},{%4,%5,%6,%7},{%8,%9},{%0,%1,%2,%3};"
                 : "+f"(c[0]), "+f"(c[1]), "+f"(c[2]), "+f"(c[3])
                 : "r"(a[0]), "r"(a[1]), "r"(a[2]), "r"(a[3]), "r"(b0), "r"(b1));
}
// A fragment (m16 x k16) from row-major [m][k] tile, stride SST
__device__ __forceinline__ void lda(uint32_t r[4], uint32_t sb, int off, int m0, int k0, int lane) {
    int row = m0 + (lane & 15);
    int col = k0 + ((lane >> 4) << 3);
    ldsm4(r, sb + (uint32_t)(off + row * SST + col) * 2);
}
// B fragment pair (n16 span x k16) from row-major [n][k] tile -> 2 n-frags (r0,r1 | r2,r3)
__device__ __forceinline__ void ldb(uint32_t r[4], uint32_t sb, int off, int n0, int k0, int lane) {
    int row = n0 + (lane & 7) + ((lane >> 4) << 3);
    int col = k0 + (((lane >> 3) & 1) << 3);
    ldsm4(r, sb + (uint32_t)(off + row * SST + col) * 2);
}

__device__ __forceinline__ uint32_t pack_split(float x) {
    __nv_bfloat16 h = __float2bfloat16(x);
    __nv_bfloat16 l = __float2bfloat16(x - __bfloat162float(h));
    return (uint32_t)__bfloat16_as_ushort(h) | ((uint32_t)__bfloat16_as_ushort(l) << 16);
}
__device__ __forceinline__ float unpack_split(uint32_t u) {
    return __bfloat162float(__ushort_as_bfloat16((unsigned short)(u & 0xFFFF))) +
           __bfloat162float(__ushort_as_bfloat16((unsigned short)(u >> 16)));
}
__device__ __forceinline__ void split4(float4 v, uint2& hw, uint2& lw) {
    __nv_bfloat16 hx = __float2bfloat16(v.x), hy = __float2bfloat16(v.y);
    __nv_bfloat16 hz = __float2bfloat16(v.z), hww = __float2bfloat16(v.w);
    __nv_bfloat16 lx = __float2bfloat16(v.x - __bfloat162float(hx));
    __nv_bfloat16 ly = __float2bfloat16(v.y - __bfloat162float(hy));
    __nv_bfloat16 lz = __float2bfloat16(v.z - __bfloat162float(hz));
    __nv_bfloat16 lww = __float2bfloat16(v.w - __bfloat162float(hww));
    hw.x = (uint32_t)__bfloat16_as_ushort(hx) | ((uint32_t)__bfloat16_as_ushort(hy) << 16);
    hw.y = (uint32_t)__bfloat16_as_ushort(hz) | ((uint32_t)__bfloat16_as_ushort(hww) << 16);
    lw.x = (uint32_t)__bfloat16_as_ushort(lx) | ((uint32_t)__bfloat16_as_ushort(ly) << 16);
    lw.y = (uint32_t)__bfloat16_as_ushort(lz) | ((uint32_t)__bfloat16_as_ushort(lww) << 16);
}
__device__ __forceinline__ void unzip4(uint4 p, uint2& hw, uint2& lw) {
    hw.x = __byte_perm(p.x, p.y, 0x5410);
    hw.y = __byte_perm(p.z, p.w, 0x5410);
    lw.x = __byte_perm(p.x, p.y, 0x7632);
    lw.y = __byte_perm(p.z, p.w, 0x7632);
}

// smem tile element offsets (bf16 units)
#define T_A_HI 0
#define T_A_LO 9216
#define T_B_HI 18432
#define T_B_LO 27648
#define SC_RED_BYTES 73728
#define SC_SMEM (73728 + 1024)
#define PJ_SMEM 73728
#define AV_V_HI 18432
#define AV_V_LO 23040
#define AV_SMEM 55296

// ---------------------------------------------------------------------------
// Kernel 0: mask repack
// ---------------------------------------------------------------------------
__global__ __launch_bounds__(256) void k_mask(const int* __restrict__ mask) {
    size_t idx = (size_t)blockIdx.x * 256 + threadIdx.x;
    int4 m = ((const int4*)mask)[idx];
    g_M[0][idx] = (m.x != 0);
    g_M[1][idx] = (m.y != 0);
    g_M[2][idx] = (m.z != 0);
    g_M[3][idx] = (m.w != 0);
}

// ---------------------------------------------------------------------------
// Kernel 0b: V transpose -> g_Vt[bh][d][j] packed bf16 split
// ---------------------------------------------------------------------------
__global__ __launch_bounds__(256) void k_vt(const float* __restrict__ v) {
    int bh = blockIdx.x, jt = blockIdx.y;
    int b = bh >> 4, h = bh & 15;
    __shared__ float T[64][68];
    int t = threadIdx.x;
    #pragma unroll
    for (int r = 0; r < 4; r++) {
        int idx = t + r * 256;
        int j = idx >> 4, d4 = idx & 15;
        float4 vv = *(const float4*)(v + (size_t)(jt * 64 + j) * (NB * DIMQ) + b * DIMQ + h * HD + d4 * 4);
        T[j][d4 * 4 + 0] = vv.x; T[j][d4 * 4 + 1] = vv.y;
        T[j][d4 * 4 + 2] = vv.z; T[j][d4 * 4 + 3] = vv.w;
    }
    __syncthreads();
    #pragma unroll
    for (int r = 0; r < 4; r++) {
        int idx = t + r * 256;
        int d = idx >> 4, j4 = idx & 15;
        uint4 o;
        o.x = pack_split(T[j4 * 4 + 0][d]);
        o.y = pack_split(T[j4 * 4 + 1][d]);
        o.z = pack_split(T[j4 * 4 + 2][d]);
        o.w = pack_split(T[j4 * 4 + 3][d]);
        *(uint4*)(g_Vt + ((size_t)bh * 64 + d) * SEQK + jt * 64 + j4 * 4) = o;
    }
}

// ---------------------------------------------------------------------------
// Kernel 1: scores. block = 128 q-rows x (bh); loops 16 k-tiles of 128.
// 8 warps in 4(M) x 2(N); warp tile 32x64.
// ---------------------------------------------------------------------------
__global__ __launch_bounds__(256) void k_scores(const float* __restrict__ q,
                                                const float* __restrict__ k) {
    extern __shared__ char smem[];
    uint32_t sb = smem_u32(smem);
    float* red = (float*)(smem + SC_RED_BYTES);
    int t = threadIdx.x, lane = t & 31, wid = t >> 5;
    int wm = wid >> 1, wn = wid & 1;
    int qt = blockIdx.x, bh = blockIdx.y;
    int b = bh >> 4, h = bh & 15;

    const float* qbase = q + b * DIMQ + h * HD;
    const float* kbase = k + b * DIMQ + h * HD;

    // load + scale + split Q tile [128 x 64]
    #pragma unroll
    for (int r = 0; r < 8; r++) {
        int idx = t + r * 256;
        int row = idx >> 4, c4 = idx & 15;
        float4 v = *(const float4*)(qbase + (size_t)(qt * 128 + row) * (NB * DIMQ) + c4 * 4);
        v.x *= QK_SCALE; v.y *= QK_SCALE; v.z *= QK_SCALE; v.w *= QK_SCALE;
        uint2 hw, lw; split4(v, hw, lw);
        *(uint2*)(smem + (size_t)(T_A_HI + row * SST + c4 * 4) * 2) = hw;
        *(uint2*)(smem + (size_t)(T_A_LO + row * SST + c4 * 4) * 2) = lw;
    }

    float rsum[4] = {0.f, 0.f, 0.f, 0.f};

    for (int kt = 0; kt < 16; kt++) {
        __syncthreads();
        // load + split K tile [128 x 64]
        #pragma unroll
        for (int r = 0; r < 8; r++) {
            int idx = t + r * 256;
            int row = idx >> 4, c4 = idx & 15;
            float4 v = *(const float4*)(kbase + (size_t)(kt * 128 + row) * (NB * DIMQ) + c4 * 4);
            uint2 hw, lw; split4(v, hw, lw);
            *(uint2*)(smem + (size_t)(T_B_HI + row * SST + c4 * 4) * 2) = hw;
            *(uint2*)(smem + (size_t)(T_B_LO + row * SST + c4 * 4) * 2) = lw;
        }
        __syncthreads();

        float acc[2][8][4] = {};
        #pragma unroll
        for (int ks = 0; ks < 4; ks++) {
            int k0 = ks * 16;
            uint32_t ah[2][4], al[2][4];
            lda(ah[0], sb, T_A_HI, wm * 32, k0, lane);
            lda(ah[1], sb, T_A_HI, wm * 32 + 16, k0, lane);
            lda(al[0], sb, T_A_LO, wm * 32, k0, lane);
            lda(al[1], sb, T_A_LO, wm * 32 + 16, k0, lane);
            uint32_t bhf[4][4], blf[4][4];
            #pragma unroll
            for (int p = 0; p < 4; p++) {
                ldb(bhf[p], sb, T_B_HI, wn * 64 + p * 16, k0, lane);
                ldb(blf[p], sb, T_B_LO, wn * 64 + p * 16, k0, lane);
            }
            #pragma unroll
            for (int p = 0; p < 4; p++)
                #pragma unroll
                for (int qq = 0; qq < 2; qq++) {
                    int nf = p * 2 + qq;
                    #pragma unroll
                    for (int mf = 0; mf < 2; mf++) {
                        mma_bf16(acc[mf][nf], ah[mf], bhf[p][qq * 2], bhf[p][qq * 2 + 1]);
                        mma_bf16(acc[mf][nf], ah[mf], blf[p][qq * 2], blf[p][qq * 2 + 1]);
                        mma_bf16(acc[mf][nf], al[mf], bhf[p][qq * 2], bhf[p][qq * 2 + 1]);
                    }
                }
        }

        // epilogue: exp * mask, pack-split store, rowsum
        #pragma unroll
        for (int mf = 0; mf < 2; mf++)
            #pragma unroll
            for (int r8 = 0; r8 < 2; r8++) {
                int li = wm * 32 + mf * 16 + r8 * 8 + (lane >> 2);
                int gi = qt * 128 + li;
                const unsigned char* mrow = g_M[b] + (size_t)gi * SEQK + kt * 128 + wn * 64;
                uint32_t* srow = g_S + ((size_t)bh * SEQQ + gi) * SEQK + kt * 128 + wn * 64;
                float rs = 0.f;
                #pragma unroll
                for (int nf = 0; nf < 8; nf++) {
                    int jj = nf * 8 + (lane & 3) * 2;
                    unsigned short mm = *(const unsigned short*)(mrow + jj);
                    float e0 = __expf(acc[mf][nf][r8 * 2 + 0]) * (float)(mm & 0xFF);
                    float e1 = __expf(acc[mf][nf][r8 * 2 + 1]) * (float)(mm >> 8);
                    rs += e0 + e1;
                    uint2 pw;
                    pw.x = pack_split(e0);
                    pw.y = pack_split(e1);
                    *(uint2*)(srow + jj) = pw;
                }
                rsum[mf * 2 + r8] += rs;
            }
    }

    // rowsum: quad shuffle then cross-warp (wn) reduce via smem
    #pragma unroll
    for (int g = 0; g < 4; g++) {
        rsum[g] += __shfl_xor_sync(0xffffffffu, rsum[g], 1);
        rsum[g] += __shfl_xor_sync(0xffffffffu, rsum[g], 2);
    }
    if ((lane & 3) == 0) {
        #pragma unroll
        for (int g = 0; g < 4; g++) {
            int li = wm * 32 + (g >> 1) * 16 + (g & 1) * 8 + (lane >> 2);
            red[li * 2 + wn] = rsum[g];
        }
    }
    __syncthreads();
    if (t < 128)
        g_rowsum[(size_t)(qt * 128 + t) * (NB * NH) + bh] = red[t * 2] + red[t * 2 + 1];
}

// ---------------------------------------------------------------------------
// Kernel 2: AV. block = 128 rows x 64 d per (bh); K-loop over 32 j-chunks of 64.
// 8 warps 4(M) x 2(N); warp tile 32x32.
// ---------------------------------------------------------------------------
__global__ __launch_bounds__(256) void k_av() {
    extern __shared__ char smem[];
    uint32_t sb = smem_u32(smem);
    int t = threadIdx.x, lane = t & 31, wid = t >> 5;
    int wm = wid >> 1, wn = wid & 1;
    int it = blockIdx.x, bh = blockIdx.y;
    int b = bh >> 4, h = bh & 15;

    const uint32_t* sbase = g_S + (size_t)bh * SEQQ * SEQK;
    const uint32_t* vbase = g_Vt + (size_t)bh * 64 * SEQK;

    float acc[2][4][4] = {};

    for (int jt = 0; jt < 32; jt++) {
        __syncthreads();
        // S tile [128 x 64] packed -> hi/lo
        #pragma unroll
        for (int r = 0; r < 8; r++) {
            int idx = t + r * 256;
            int row = idx >> 4, c4 = idx & 15;
            uint4 p = *(const uint4*)(sbase + (size_t)(it * 128 + row) * SEQK + jt * 64 + c4 * 4);
            uint2 hw, lw; unzip4(p, hw, lw);
            *(uint2*)(smem + (size_t)(T_A_HI + row * SST + c4 * 4) * 2) = hw;
            *(uint2*)(smem + (size_t)(T_A_LO + row * SST + c4 * 4) * 2) = lw;
        }
        // Vt tile [64 x 64] packed -> hi/lo
        #pragma unroll
        for (int r = 0; r < 4; r++) {
            int idx = t + r * 256;
            int row = idx >> 4, c4 = idx & 15;
            uint4 p = *(const uint4*)(vbase + (size_t)row * SEQK + jt * 64 + c4 * 4);
            uint2 hw, lw; unzip4(p, hw, lw);
            *(uint2*)(smem + (size_t)(AV_V_HI + row * SST + c4 * 4) * 2) = hw;
            *(uint2*)(smem + (size_t)(AV_V_LO + row * SST + c4 * 4) * 2) = lw;
        }
        __syncthreads();

        #pragma unroll
        for (int ks = 0; ks < 4; ks++) {
            int k0 = ks * 16;
            uint32_t ah[2][4], al[2][4];
            lda(ah[0], sb, T_A_HI, wm * 32, k0, lane);
            lda(ah[1], sb, T_A_HI, wm * 32 + 16, k0, lane);
            lda(al[0], sb, T_A_LO, wm * 32, k0, lane);
            lda(al[1], sb, T_A_LO, wm * 32 + 16, k0, lane);
            uint32_t bhf[2][4], blf[2][4];
            #pragma unroll
            for (int p = 0; p < 2; p++) {
                ldb(bhf[p], sb, AV_V_HI, wn * 32 + p * 16, k0, lane);
                ldb(blf[p], sb, AV_V_LO, wn * 32 + p * 16, k0, lane);
            }
            #pragma unroll
            for (int p = 0; p < 2; p++)
                #pragma unroll
                for (int qq = 0; qq < 2; qq++) {
                    int nf = p * 2 + qq;
                    #pragma unroll
                    for (int mf = 0; mf < 2; mf++) {
                        mma_bf16(acc[mf][nf], ah[mf], bhf[p][qq * 2], bhf[p][qq * 2 + 1]);
                        mma_bf16(acc[mf][nf], ah[mf], blf[p][qq * 2], blf[p][qq * 2 + 1]);
                        mma_bf16(acc[mf][nf], al[mf], bhf[p][qq * 2], bhf[p][qq * 2 + 1]);
                    }
                }
        }
    }

    // epilogue: normalize, pack-split, store to g_xp
    #pragma unroll
    for (int mf = 0; mf < 2; mf++)
        #pragma unroll
        for (int r8 = 0; r8 < 2; r8++) {
            int li = wm * 32 + mf * 16 + r8 * 8 + (lane >> 2);
            int gi = it * 128 + li;
            float rinv = 1.0f / g_rowsum[(size_t)gi * (NB * NH) + bh];
            uint32_t* dst = g_xp + (size_t)(gi * NB + b) * DIMQ + h * HD + wn * 32;
            #pragma unroll
            for (int nf = 0; nf < 4; nf++) {
                int dd = nf * 8 + (lane & 3) * 2;
                uint2 pw;
                pw.x = pack_split(acc[mf][nf][r8 * 2 + 0] * rinv);
                pw.y = pack_split(acc[mf][nf][r8 * 2 + 1] * rinv);
                *(uint2*)(dst + dd) = pw;
            }
        }
}

// ---------------------------------------------------------------------------
// Kernel 3: projection out = x @ W^T + bias. block 128x128; K loop 16 x 64.
// ---------------------------------------------------------------------------
__global__ __launch_bounds__(256) void k_proj(const float* __restrict__ W,
                                              const float* __restrict__ bias,
                                              float* __restrict__ out) {
    extern __shared__ char smem[];
    uint32_t sb = smem_u32(smem);
    int t = threadIdx.x, lane = t & 31, wid = t >> 5;
    int wm = wid >> 1, wn = wid & 1;
    int rt = blockIdx.x, nt = blockIdx.y;

    float acc[2][8][4] = {};

    for (int mt = 0; mt < 16; mt++) {
        __syncthreads();
        // A: x packed [128 x 64]
        #pragma unroll
        for (int r = 0; r < 8; r++) {
            int idx = t + r * 256;
            int row = idx >> 4, c4 = idx & 15;
            uint4 p = *(const uint4*)(g_xp + (size_t)(rt * 128 + row) * DIMQ + mt * 64 + c4 * 4);
            uint2 hw, lw; unzip4(p, hw, lw);
            *(uint2*)(smem + (size_t)(T_A_HI + row * SST + c4 * 4) * 2) = hw;
            *(uint2*)(smem + (size_t)(T_A_LO + row * SST + c4 * 4) * 2) = lw;
        }
        // B: W fp32 [128 x 64] -> split
        #pragma unroll
        for (int r = 0; r < 8; r++) {
            int idx = t + r * 256;
            int row = idx >> 4, c4 = idx & 15;
            float4 v = *(const float4*)(W + (size_t)(nt * 128 + row) * DIMQ + mt * 64 + c4 * 4);
            uint2 hw, lw; split4(v, hw, lw);
            *(uint2*)(smem + (size_t)(T_B_HI + row * SST + c4 * 4) * 2) = hw;
            *(uint2*)(smem + (size_t)(T_B_LO + row * SST + c4 * 4) * 2) = lw;
        }
        __syncthreads();

        #pragma unroll
        for (int ks = 0; ks < 4; ks++) {
            int k0 = ks * 16;
            uint32_t ah[2][4], al[2][4];
            lda(ah[0], sb, T_A_HI, wm * 32, k0, lane);
            lda(ah[1], sb, T_A_HI, wm * 32 + 16, k0, lane);
            lda(al[0], sb, T_A_LO, wm * 32, k0, lane);
            lda(al[1], sb, T_A_LO, wm * 32 + 16, k0, lane);
            uint32_t bhf[4][4], blf[4][4];
            #pragma unroll
            for (int p = 0; p < 4; p++) {
                ldb(bhf[p], sb, T_B_HI, wn * 64 + p * 16, k0, lane);
                ldb(blf[p], sb, T_B_LO, wn * 64 + p * 16, k0, lane);
            }
            #pragma unroll
            for (int p = 0; p < 4; p++)
                #pragma unroll
                for (int qq = 0; qq < 2; qq++) {
                    int nf = p * 2 + qq;
                    #pragma unroll
                    for (int mf = 0; mf < 2; mf++) {
                        mma_bf16(acc[mf][nf], ah[mf], bhf[p][qq * 2], bhf[p][qq * 2 + 1]);
                        mma_bf16(acc[mf][nf], ah[mf], blf[p][qq * 2], blf[p][qq * 2 + 1]);
                        mma_bf16(acc[mf][nf], al[mf], bhf[p][qq * 2], bhf[p][qq * 2 + 1]);
                    }
                }
        }
    }

    // epilogue: + bias, fp32 store
    #pragma unroll
    for (int mf = 0; mf < 2; mf++)
        #pragma unroll
        for (int r8 = 0; r8 < 2; r8++) {
            int row = rt * 128 + wm * 32 + mf * 16 + r8 * 8 + (lane >> 2);
            float* orow = out + (size_t)row * DIMQ + nt * 128 + wn * 64;
            const float* brow = bias + nt * 128 + wn * 64;
            #pragma unroll
            for (int nf = 0; nf < 8; nf++) {
                int cc = nf * 8 + (lane & 3) * 2;
                float2 o;
                o.x = acc[mf][nf][r8 * 2 + 0] + brow[cc];
                o.y = acc[mf][nf][r8 * 2 + 1] + brow[cc + 1];
                *(float2*)(orow + cc) = o;
            }
        }
}

// ---------------------------------------------------------------------------
// Kernel 4: normalized attn write with transpose to [i][j][b][h]
// ---------------------------------------------------------------------------
__global__ __launch_bounds__(256) void k_attnT(float* __restrict__ attn) {
    int i = blockIdx.x, jt = blockIdx.y;
    __shared__ float T[64][68];
    __shared__ float rinv_s[64];
    int t = threadIdx.x;
    if (t < 64) rinv_s[t] = 1.0f / g_rowsum[(size_t)i * 64 + t];
    {
        int c = t >> 2, l4 = t & 3;
        const uint32_t* src = g_S + ((size_t)c * SEQQ + i) * SEQK + jt * 64 + l4 * 16;
        #pragma unroll
        for (int r = 0; r < 4; r++) {
            uint4 pv = *(const uint4*)(src + r * 4);
            int j = l4 * 16 + r * 4;
            T[j + 0][c] = unpack_split(pv.x); T[j + 1][c] = unpack_split(pv.y);
            T[j + 2][c] = unpack_split(pv.z); T[j + 3][c] = unpack_split(pv.w);
        }
    }
    __syncthreads();
    {
        int c0 = (t & 15) * 4;
        int jb = t >> 4;
        #pragma unroll
        for (int r = 0; r < 4; r++) {
            int j = jb + r * 16;
            float4 o;
            o.x = T[j][c0 + 0] * rinv_s[c0 + 0];
            o.y = T[j][c0 + 1] * rinv_s[c0 + 1];
            o.z = T[j][c0 + 2] * rinv_s[c0 + 2];
            o.w = T[j][c0 + 3] * rinv_s[c0 + 3];
            *(float4*)(attn + ((size_t)i * SEQK + jt * 64 + j) * 64 + c0) = o;
        }
    }
}

// ---------------------------------------------------------------------------
extern "C" void kernel_launch(void* const* d_in, const int* in_sizes, int n_in,
                              void* d_out, int out_size) {
    const float* q    = (const float*)d_in[0];
    const float* k    = (const float*)d_in[1];
    const float* v    = (const float*)d_in[2];
    const int*   mask = (const int*)d_in[3];
    const float* W    = (const float*)d_in[4];
    const float* bias = (const float*)d_in[5];
    float* out = (float*)d_out;

    cudaFuncSetAttribute(k_scores, cudaFuncAttributeMaxDynamicSharedMemorySize, SC_SMEM);
    cudaFuncSetAttribute(k_av,     cudaFuncAttributeMaxDynamicSharedMemorySize, AV_SMEM);
    cudaFuncSetAttribute(k_proj,   cudaFuncAttributeMaxDynamicSharedMemorySize, PJ_SMEM);

    k_mask<<<(SEQQ * SEQK) / 256, 256>>>(mask);
    k_vt<<<dim3(NB * NH, SEQK / 64), 256>>>(v);
    k_scores<<<dim3(SEQQ / 128, NB * NH), 256, SC_SMEM>>>(q, k);
    k_av<<<dim3(SEQQ / 128, NB * NH), 256, AV_SMEM>>>();
    k_proj<<<dim3(SEQQ * NB / 128, DIMQ / 128), 256, PJ_SMEM>>>(W, bias, out);

    const long long OUT_ELEMS  = (long long)SEQQ * NB * DIMQ;
    const long long ATTN_ELEMS = (long long)SEQQ * SEQK * NB * NH;
    if ((long long)out_size >= OUT_ELEMS + ATTN_ELEMS) {
        float* attn = out + OUT_ELEMS;
        k_attnT<<<dim3(SEQQ, SEQK / 64), 256>>>(attn);
    }
}

// round 4
// speedup vs baseline: 3.5229x; 1.5256x over previous
#include <cuda_runtime.h>
#include <cuda_bf16.h>
#include <cstdint>
#include <math.h>

#define SEQQ 2048
#define SEQK 2048
#define NB   4
#define NH   16
#define HD   64
#define DIMQ 1024
#define QK_SCALE 0.125f
#define SST  72    // Q/K smem row stride (bf16 elems)
#define SSTV 136   // V smem row stride (bf16 elems), 128-wide j

// ---------------- static device scratch ----------------
__device__ uint32_t g_S[(size_t)NB * NH * SEQQ * SEQK];     // packed bf16 hi|lo exp-scores
__device__ float    g_rowsum[(size_t)SEQQ * NB * NH];       // [i][bh]
__device__ uint32_t g_xp[(size_t)SEQQ * NB * DIMQ];         // packed bf16 hi|lo attention out
__device__ uint32_t g_Vt[(size_t)NB * NH * HD * SEQK];      // packed V transposed [bh][d][j]
__device__ unsigned char g_M[NB][(size_t)SEQQ * SEQK];      // mask byte planes

// ---------------- helpers ----------------
__device__ __forceinline__ uint32_t smem_u32(const void* p) {
    uint32_t a;
    asm("{ .reg .u64 t; cvta.to.shared.u64 t, %1; cvt.u32.u64 %0, t; }" : "=r"(a) : "l"(p));
    return a;
}
__device__ __forceinline__ void ldsm4(uint32_t r[4], uint32_t addr) {
    asm volatile("ldmatrix.sync.aligned.m8n8.x4.shared.b16 {%0,%1,%2,%3}, [%4];"
                 : "=r"(r[0]), "=r"(r[1]), "=r"(r[2]), "=r"(r[3]) : "r"(addr));
}
__device__ __forceinline__ void mma_bf16(float* c, const uint32_t* a, uint32_t b0, uint32_t b1) {
    asm volatile("mma.sync.aligned.m16n8k16.row.col.f32.bf16.bf16.f32 "
                 "{%0,%1,%2,%3},{%4,%5,%6,%7},{%8,%9},{%0,%1,%2,%3};"
                 : "+f"(c[0]), "+f"(c[1]), "+f"(c[2]), "+f"(c[3])
                 : "r"(a[0]), "r"(a[1]), "r"(a[2]), "r"(a[3]), "r"(b0), "r"(b1));
}
// A fragment (m16 x k16) from row-major [m][k] tile
__device__ __forceinline__ void lda(uint32_t r[4], uint32_t sb, int off, int stride,
                                    int m0, int k0, int lane) {
    int row = m0 + (lane & 15);
    int col = k0 + ((lane >> 4) << 3);
    ldsm4(r, sb + (uint32_t)(off + row * stride + col) * 2);
}
// B fragment pair (n16 span x k16) from row-major [n][k] tile -> 2 n8 frags
__device__ __forceinline__ void ldb(uint32_t r[4], uint32_t sb, int off, int stride,
                                    int n0, int k0, int lane) {
    int row = n0 + (lane & 7) + ((lane >> 4) << 3);
    int col = k0 + (((lane >> 3) & 1) << 3);
    ldsm4(r, sb + (uint32_t)(off + row * stride + col) * 2);
}

__device__ __forceinline__ uint32_t pack_split(float x) {
    __nv_bfloat16 h = __float2bfloat16(x);
    __nv_bfloat16 l = __float2bfloat16(x - __bfloat162float(h));
    return (uint32_t)__bfloat16_as_ushort(h) | ((uint32_t)__bfloat16_as_ushort(l) << 16);
}
__device__ __forceinline__ float unpack_split(uint32_t u) {
    return __bfloat162float(__ushort_as_bfloat16((unsigned short)(u & 0xFFFF))) +
           __bfloat162float(__ushort_as_bfloat16((unsigned short)(u >> 16)));
}
// (e0,e1) -> hi pair word (e0 low), lo pair word
__device__ __forceinline__ void split2(float e0, float e1, uint32_t& hw, uint32_t& lw) {
    __nv_bfloat162 hp = __floats2bfloat162_rn(e0, e1);
    float l0 = e0 - __bfloat162float(hp.x);
    float l1 = e1 - __bfloat162float(hp.y);
    __nv_bfloat162 lp = __floats2bfloat162_rn(l0, l1);
    hw = *(uint32_t*)&hp;
    lw = *(uint32_t*)&lp;
}
__device__ __forceinline__ void split4(float4 v, uint2& hw, uint2& lw) {
    split2(v.x, v.y, hw.x, lw.x);
    split2(v.z, v.w, hw.y, lw.y);
}
__device__ __forceinline__ void unzip4(uint4 p, uint2& hw, uint2& lw) {
    hw.x = __byte_perm(p.x, p.y, 0x5410);
    hw.y = __byte_perm(p.z, p.w, 0x5410);
    lw.x = __byte_perm(p.x, p.y, 0x7632);
    lw.y = __byte_perm(p.z, p.w, 0x7632);
}

// ---- fused kernel smem layout (bytes) ----
#define F_Q_HI 0
#define F_Q_LO 18432
#define F_K_HI 36864
#define F_K_LO 55296
#define F_V_HI 73728
#define F_V_LO 91136
#define F_SMEM 108544

// proj smem (elem offsets like R3)
#define T_A_HI 0
#define T_A_LO 9216
#define T_B_HI 18432
#define T_B_LO 27648
#define PJ_SMEM 73728

// ---------------------------------------------------------------------------
// Kernel 0: mask repack
// ---------------------------------------------------------------------------
__global__ __launch_bounds__(256) void k_mask(const int* __restrict__ mask) {
    size_t idx = (size_t)blockIdx.x * 256 + threadIdx.x;
    int4 m = ((const int4*)mask)[idx];
    g_M[0][idx] = (m.x != 0);
    g_M[1][idx] = (m.y != 0);
    g_M[2][idx] = (m.z != 0);
    g_M[3][idx] = (m.w != 0);
}

// ---------------------------------------------------------------------------
// Kernel 0b: V transpose -> g_Vt[bh][d][j] packed bf16 split
// ---------------------------------------------------------------------------
__global__ __launch_bounds__(256) void k_vt(const float* __restrict__ v) {
    int bh = blockIdx.x, jt = blockIdx.y;
    int b = bh >> 4, h = bh & 15;
    __shared__ float T[64][68];
    int t = threadIdx.x;
    #pragma unroll
    for (int r = 0; r < 4; r++) {
        int idx = t + r * 256;
        int j = idx >> 4, d4 = idx & 15;
        float4 vv = *(const float4*)(v + (size_t)(jt * 64 + j) * (NB * DIMQ) + b * DIMQ + h * HD + d4 * 4);
        T[j][d4 * 4 + 0] = vv.x; T[j][d4 * 4 + 1] = vv.y;
        T[j][d4 * 4 + 2] = vv.z; T[j][d4 * 4 + 3] = vv.w;
    }
    __syncthreads();
    #pragma unroll
    for (int r = 0; r < 4; r++) {
        int idx = t + r * 256;
        int d = idx >> 4, j4 = idx & 15;
        uint4 o;
        o.x = pack_split(T[j4 * 4 + 0][d]);
        o.y = pack_split(T[j4 * 4 + 1][d]);
        o.z = pack_split(T[j4 * 4 + 2][d]);
        o.w = pack_split(T[j4 * 4 + 3][d]);
        *(uint4*)(g_Vt + ((size_t)bh * 64 + d) * SEQK + jt * 64 + j4 * 4) = o;
    }
}

// ---------------------------------------------------------------------------
// Fused attention: per block = 128 q-rows x one (b,h).
// 8 warps, each owns 16 q-rows x full N. Loop over 16 j-chunks of 128:
//   MMA1 (Q.K^T split-bf16) -> exp*mask -> pack S (store gmem) ->
//   accumulator frags become A-frags for MMA2 (S.V) -> accumulate O.
// Rowsum finishes in-register; O normalized + stored packed.
// ---------------------------------------------------------------------------
__global__ __launch_bounds__(256) void k_attn(const float* __restrict__ q,
                                              const float* __restrict__ k) {
    extern __shared__ char smem[];
    uint32_t sb = smem_u32(smem);
    int t = threadIdx.x, lane = t & 31, wid = t >> 5;
    int qt = blockIdx.x, bh = blockIdx.y;
    int b = bh >> 4, h = bh & 15;

    const float* qbase = q + b * DIMQ + h * HD;
    const float* kbase = k + b * DIMQ + h * HD;
    const uint32_t* vbase = g_Vt + (size_t)bh * 64 * SEQK;

    // load + scale + split Q tile [128 x 64]
    #pragma unroll
    for (int r = 0; r < 8; r++) {
        int idx = t + r * 256;
        int row = idx >> 4, c4 = idx & 15;
        float4 v = *(const float4*)(qbase + (size_t)(qt * 128 + row) * (NB * DIMQ) + c4 * 4);
        v.x *= QK_SCALE; v.y *= QK_SCALE; v.z *= QK_SCALE; v.w *= QK_SCALE;
        uint2 hw, lw; split4(v, hw, lw);
        *(uint2*)(smem + F_Q_HI + (size_t)(row * SST + c4 * 4) * 2) = hw;
        *(uint2*)(smem + F_Q_LO + (size_t)(row * SST + c4 * 4) * 2) = lw;
    }

    int r0 = wid * 16 + (lane >> 2);      // local row (and r0+8)
    int gi0 = qt * 128 + r0;
    const unsigned char* mrow0 = g_M[b] + (size_t)gi0 * SEQK;
    const unsigned char* mrow1 = mrow0 + (size_t)8 * SEQK;
    uint32_t* srow0 = g_S + ((size_t)bh * SEQQ + gi0) * SEQK;
    uint32_t* srow1 = srow0 + (size_t)8 * SEQK;

    float oacc[8][4] = {};
    float rsum0 = 0.f, rsum1 = 0.f;

    for (int kt = 0; kt < 16; kt++) {
        __syncthreads();
        // K chunk [128 x 64] fp32 -> split
        #pragma unroll
        for (int r = 0; r < 8; r++) {
            int idx = t + r * 256;
            int row = idx >> 4, c4 = idx & 15;
            float4 v = *(const float4*)(kbase + (size_t)(kt * 128 + row) * (NB * DIMQ) + c4 * 4);
            uint2 hw, lw; split4(v, hw, lw);
            *(uint2*)(smem + F_K_HI + (size_t)(row * SST + c4 * 4) * 2) = hw;
            *(uint2*)(smem + F_K_LO + (size_t)(row * SST + c4 * 4) * 2) = lw;
        }
        // V chunk [64 d x 128 j] packed -> split planes
        #pragma unroll
        for (int r = 0; r < 8; r++) {
            int idx = t + r * 256;
            int row = idx >> 5, c4 = idx & 31;       // 64 rows x 32 uint4-groups
            uint4 p = *(const uint4*)(vbase + (size_t)row * SEQK + kt * 128 + c4 * 4);
            uint2 hw, lw; unzip4(p, hw, lw);
            *(uint2*)(smem + F_V_HI + (size_t)(row * SSTV + c4 * 4) * 2) = hw;
            *(uint2*)(smem + F_V_LO + (size_t)(row * SSTV + c4 * 4) * 2) = lw;
        }
        __syncthreads();

        // ---- MMA1: S(16x128) = Q(16x64) . K^T ----
        float cf[16][4] = {};
        #pragma unroll
        for (int ks = 0; ks < 4; ks++) {
            int k0 = ks * 16;
            uint32_t ah[4], al[4];
            lda(ah, sb, F_Q_HI / 2, SST, wid * 16, k0, lane);
            lda(al, sb, F_Q_LO / 2, SST, wid * 16, k0, lane);
            #pragma unroll
            for (int p = 0; p < 8; p++) {
                uint32_t bhf[4], blf[4];
                ldb(bhf, sb, F_K_HI / 2, SST, p * 16, k0, lane);
                ldb(blf, sb, F_K_LO / 2, SST, p * 16, k0, lane);
                #pragma unroll
                for (int qq = 0; qq < 2; qq++) {
                    int nf = p * 2 + qq;
                    mma_bf16(cf[nf], ah, bhf[qq * 2], bhf[qq * 2 + 1]);
                    mma_bf16(cf[nf], ah, blf[qq * 2], blf[qq * 2 + 1]);
                    mma_bf16(cf[nf], al, bhf[qq * 2], bhf[qq * 2 + 1]);
                }
            }
        }

        // ---- epilogue: exp*mask, split to hi/lo words, store S, rowsum ----
        uint32_t shw[16][2], slw[16][2];   // [nf][row0/row1] bf16x2 pairs
        #pragma unroll
        for (int nf = 0; nf < 16; nf++) {
            int jj = kt * 128 + nf * 8 + (lane & 3) * 2;
            unsigned short m0 = *(const unsigned short*)(mrow0 + jj);
            unsigned short m1 = *(const unsigned short*)(mrow1 + jj);
            float e00 = __expf(cf[nf][0]) * (float)(m0 & 0xFF);
            float e01 = __expf(cf[nf][1]) * (float)(m0 >> 8);
            float e10 = __expf(cf[nf][2]) * (float)(m1 & 0xFF);
            float e11 = __expf(cf[nf][3]) * (float)(m1 >> 8);
            rsum0 += e00 + e01;
            rsum1 += e10 + e11;
            split2(e00, e01, shw[nf][0], slw[nf][0]);
            split2(e10, e11, shw[nf][1], slw[nf][1]);
            uint2 w0, w1;
            w0.x = __byte_perm(shw[nf][0], slw[nf][0], 0x5410);
            w0.y = __byte_perm(shw[nf][0], slw[nf][0], 0x7632);
            w1.x = __byte_perm(shw[nf][1], slw[nf][1], 0x5410);
            w1.y = __byte_perm(shw[nf][1], slw[nf][1], 0x7632);
            *(uint2*)(srow0 + jj) = w0;
            *(uint2*)(srow1 + jj) = w1;
        }

        // ---- MMA2: O(16x64) += S(16x128) . V ----
        #pragma unroll
        for (int s = 0; s < 8; s++) {
            uint32_t ah2[4] = { shw[2 * s][0], shw[2 * s][1], shw[2 * s + 1][0], shw[2 * s + 1][1] };
            uint32_t al2[4] = { slw[2 * s][0], slw[2 * s][1], slw[2 * s + 1][0], slw[2 * s + 1][1] };
            int k0 = s * 16;
            #pragma unroll
            for (int p = 0; p < 4; p++) {
                uint32_t bhf[4], blf[4];
                ldb(bhf, sb, F_V_HI / 2, SSTV, p * 16, k0, lane);
                ldb(blf, sb, F_V_LO / 2, SSTV, p * 16, k0, lane);
                #pragma unroll
                for (int qq = 0; qq < 2; qq++) {
                    int nf = p * 2 + qq;
                    mma_bf16(oacc[nf], ah2, bhf[qq * 2], bhf[qq * 2 + 1]);
                    mma_bf16(oacc[nf], ah2, blf[qq * 2], blf[qq * 2 + 1]);
                    mma_bf16(oacc[nf], al2, bhf[qq * 2], bhf[qq * 2 + 1]);
                }
            }
        }
    }

    // rowsum across quad (4 lanes share a row)
    rsum0 += __shfl_xor_sync(0xffffffffu, rsum0, 1);
    rsum0 += __shfl_xor_sync(0xffffffffu, rsum0, 2);
    rsum1 += __shfl_xor_sync(0xffffffffu, rsum1, 1);
    rsum1 += __shfl_xor_sync(0xffffffffu, rsum1, 2);
    if ((lane & 3) == 0) {
        g_rowsum[(size_t)gi0 * (NB * NH) + bh] = rsum0;
        g_rowsum[(size_t)(gi0 + 8) * (NB * NH) + bh] = rsum1;
    }
    float rinv0 = 1.0f / rsum0, rinv1 = 1.0f / rsum1;

    // O epilogue: normalize, pack-split, store g_xp
    uint32_t* dst0 = g_xp + (size_t)(gi0 * NB + b) * DIMQ + h * HD;
    uint32_t* dst1 = g_xp + (size_t)((gi0 + 8) * NB + b) * DIMQ + h * HD;
    #pragma unroll
    for (int nf = 0; nf < 8; nf++) {
        int dd = nf * 8 + (lane & 3) * 2;
        uint2 p0, p1;
        p0.x = pack_split(oacc[nf][0] * rinv0);
        p0.y = pack_split(oacc[nf][1] * rinv0);
        p1.x = pack_split(oacc[nf][2] * rinv1);
        p1.y = pack_split(oacc[nf][3] * rinv1);
        *(uint2*)(dst0 + dd) = p0;
        *(uint2*)(dst1 + dd) = p1;
    }
}

// ---------------------------------------------------------------------------
// Kernel 3: projection out = x @ W^T + bias. block 128x128; K loop 16 x 64.
// ---------------------------------------------------------------------------
__global__ __launch_bounds__(256) void k_proj(const float* __restrict__ W,
                                              const float* __restrict__ bias,
                                              float* __restrict__ out) {
    extern __shared__ char smem[];
    uint32_t sb = smem_u32(smem);
    int t = threadIdx.x, lane = t & 31, wid = t >> 5;
    int wm = wid >> 1, wn = wid & 1;
    int rt = blockIdx.x, nt = blockIdx.y;

    float acc[2][8][4] = {};

    for (int mt = 0; mt < 16; mt++) {
        __syncthreads();
        #pragma unroll
        for (int r = 0; r < 8; r++) {
            int idx = t + r * 256;
            int row = idx >> 4, c4 = idx & 15;
            uint4 p = *(const uint4*)(g_xp + (size_t)(rt * 128 + row) * DIMQ + mt * 64 + c4 * 4);
            uint2 hw, lw; unzip4(p, hw, lw);
            *(uint2*)(smem + (size_t)(T_A_HI + row * SST + c4 * 4) * 2) = hw;
            *(uint2*)(smem + (size_t)(T_A_LO + row * SST + c4 * 4) * 2) = lw;
        }
        #pragma unroll
        for (int r = 0; r < 8; r++) {
            int idx = t + r * 256;
            int row = idx >> 4, c4 = idx & 15;
            float4 v = *(const float4*)(W + (size_t)(nt * 128 + row) * DIMQ + mt * 64 + c4 * 4);
            uint2 hw, lw; split4(v, hw, lw);
            *(uint2*)(smem + (size_t)(T_B_HI + row * SST + c4 * 4) * 2) = hw;
            *(uint2*)(smem + (size_t)(T_B_LO + row * SST + c4 * 4) * 2) = lw;
        }
        __syncthreads();

        #pragma unroll
        for (int ks = 0; ks < 4; ks++) {
            int k0 = ks * 16;
            uint32_t ah[2][4], al[2][4];
            lda(ah[0], sb, T_A_HI, SST, wm * 32, k0, lane);
            lda(ah[1], sb, T_A_HI, SST, wm * 32 + 16, k0, lane);
            lda(al[0], sb, T_A_LO, SST, wm * 32, k0, lane);
            lda(al[1], sb, T_A_LO, SST, wm * 32 + 16, k0, lane);
            #pragma unroll
            for (int p = 0; p < 4; p++) {
                uint32_t bhf[4], blf[4];
                ldb(bhf, sb, T_B_HI, SST, wn * 64 + p * 16, k0, lane);
                ldb(blf, sb, T_B_LO, SST, wn * 64 + p * 16, k0, lane);
                #pragma unroll
                for (int qq = 0; qq < 2; qq++) {
                    int nf = p * 2 + qq;
                    #pragma unroll
                    for (int mf = 0; mf < 2; mf++) {
                        mma_bf16(acc[mf][nf], ah[mf], bhf[qq * 2], bhf[qq * 2 + 1]);
                        mma_bf16(acc[mf][nf], ah[mf], blf[qq * 2], blf[qq * 2 + 1]);
                        mma_bf16(acc[mf][nf], al[mf], bhf[qq * 2], bhf[qq * 2 + 1]);
                    }
                }
            }
        }
    }

    #pragma unroll
    for (int mf = 0; mf < 2; mf++)
        #pragma unroll
        for (int r8 = 0; r8 < 2; r8++) {
            int row = rt * 128 + wm * 32 + mf * 16 + r8 * 8 + (lane >> 2);
            float* orow = out + (size_t)row * DIMQ + nt * 128 + wn * 64;
            const float* brow = bias + nt * 128 + wn * 64;
            #pragma unroll
            for (int nf = 0; nf < 8; nf++) {
                int cc = nf * 8 + (lane & 3) * 2;
                float2 o;
                o.x = acc[mf][nf][r8 * 2 + 0] + brow[cc];
                o.y = acc[mf][nf][r8 * 2 + 1] + brow[cc + 1];
                *(float2*)(orow + cc) = o;
            }
        }
}

// ---------------------------------------------------------------------------
// Kernel 4: normalized attn write with transpose to [i][j][b][h]
// ---------------------------------------------------------------------------
__global__ __launch_bounds__(256) void k_attnT(float* __restrict__ attn) {
    int i = blockIdx.x, jt = blockIdx.y;
    __shared__ float T[64][68];
    __shared__ float rinv_s[64];
    int t = threadIdx.x;
    if (t < 64) rinv_s[t] = 1.0f / g_rowsum[(size_t)i * 64 + t];
    {
        int c = t >> 2, l4 = t & 3;
        const uint32_t* src = g_S + ((size_t)c * SEQQ + i) * SEQK + jt * 64 + l4 * 16;
        #pragma unroll
        for (int r = 0; r < 4; r++) {
            uint4 pv = *(const uint4*)(src + r * 4);
            int j = l4 * 16 + r * 4;
            T[j + 0][c] = unpack_split(pv.x); T[j + 1][c] = unpack_split(pv.y);
            T[j + 2][c] = unpack_split(pv.z); T[j + 3][c] = unpack_split(pv.w);
        }
    }
    __syncthreads();
    {
        int c0 = (t & 15) * 4;
        int jb = t >> 4;
        #pragma unroll
        for (int r = 0; r < 4; r++) {
            int j = jb + r * 16;
            float4 o;
            o.x = T[j][c0 + 0] * rinv_s[c0 + 0];
            o.y = T[j][c0 + 1] * rinv_s[c0 + 1];
            o.z = T[j][c0 + 2] * rinv_s[c0 + 2];
            o.w = T[j][c0 + 3] * rinv_s[c0 + 3];
            *(float4*)(attn + ((size_t)i * SEQK + jt * 64 + j) * 64 + c0) = o;
        }
    }
}

// ---------------------------------------------------------------------------
extern "C" void kernel_launch(void* const* d_in, const int* in_sizes, int n_in,
                              void* d_out, int out_size) {
    const float* q    = (const float*)d_in[0];
    const float* k    = (const float*)d_in[1];
    const float* v    = (const float*)d_in[2];
    const int*   mask = (const int*)d_in[3];
    const float* W    = (const float*)d_in[4];
    const float* bias = (const float*)d_in[5];
    float* out = (float*)d_out;

    cudaFuncSetAttribute(k_attn, cudaFuncAttributeMaxDynamicSharedMemorySize, F_SMEM);
    cudaFuncSetAttribute(k_proj, cudaFuncAttributeMaxDynamicSharedMemorySize, PJ_SMEM);

    k_mask<<<(SEQQ * SEQK) / 256, 256>>>(mask);
    k_vt<<<dim3(NB * NH, SEQK / 64), 256>>>(v);
    k_attn<<<dim3(SEQQ / 128, NB * NH), 256, F_SMEM>>>(q, k);
    k_proj<<<dim3(SEQQ * NB / 128, DIMQ / 128), 256, PJ_SMEM>>>(W, bias, out);

    const long long OUT_ELEMS  = (long long)SEQQ * NB * DIMQ;
    const long long ATTN_ELEMS = (long long)SEQQ * SEQK * NB * NH;
    if ((long long)out_size >= OUT_ELEMS + ATTN_ELEMS) {
        float* attn = out + OUT_ELEMS;
        k_attnT<<<dim3(SEQQ, SEQK / 64), 256>>>(attn);
    }
}